// round 17
// baseline (speedup 1.0000x reference)
#include <cuda_runtime.h>
#include <cuda_bf16.h>

#define NN 4096
#define DIN 512
#define DH1 256
#define DH2 64
#define ALPHA 0.2f

__device__ __forceinline__ unsigned f2tf(float f) {
    unsigned u; asm("cvt.rna.tf32.f32 %0, %1;" : "=r"(u) : "f"(f)); return u;
}
__device__ __forceinline__ void mma_tf32(float* c, const unsigned* a, unsigned b0, unsigned b1) {
    asm volatile("mma.sync.aligned.m16n8k8.row.col.f32.tf32.tf32.f32 "
                 "{%0,%1,%2,%3}, {%4,%5,%6,%7}, {%8,%9}, {%0,%1,%2,%3};"
                 : "+f"(c[0]), "+f"(c[1]), "+f"(c[2]), "+f"(c[3])
                 : "r"(a[0]), "r"(a[1]), "r"(a[2]), "r"(a[3]), "r"(b0), "r"(b1));
}
__device__ __forceinline__ void cp_async16(void* dst_smem, const void* src) {
    unsigned d = (unsigned)__cvta_generic_to_shared(dst_smem);
    asm volatile("cp.async.cg.shared.global [%0], [%1], 16;" :: "r"(d), "l"(src));
}
#define CP_COMMIT() asm volatile("cp.async.commit_group;")
#define CP_WAIT0()  asm volatile("cp.async.wait_group 0;")
#define CP_WAIT1()  asm volatile("cp.async.wait_group 1;")

// fma/alu-only exp2-based exp and sigmoid
__device__ __forceinline__ float fast_exp(float x) {
    float u = x * 1.44269504f;
    u = fminf(fmaxf(u, -60.f), 60.f);
    float s = u + 12582912.f;
    int n = __float_as_int(s) - 0x4B400000;
    float f = u - (s - 12582912.f);
    float p = 0.00133336f;
    p = fmaf(p, f, 0.00961813f);
    p = fmaf(p, f, 0.05550411f);
    p = fmaf(p, f, 0.24022651f);
    p = fmaf(p, f, 0.69314718f);
    p = fmaf(p, f, 1.0f);
    return __int_as_float(__float_as_int(p) + (n << 23));
}
__device__ __forceinline__ float fast_sigmoid(float x) {
    float e = fast_exp(-x);
    float d = 1.f + e;
    float y = __int_as_float(0x7EF311C3 - __float_as_int(d));
    y = y * fmaf(-d, y, 2.f);
    y = y * fmaf(-d, y, 2.f);
    return y;
}

// ---------------- device scratch (no allocations allowed) ----------------
__device__ float    g_h0[NN * DH1];
__device__ unsigned g_h0t[NN * DH1];
__device__ float    g_hidden[NN * DH1];
__device__ float    g_h1[NN * DH2];
__device__ unsigned g_h1t[NN * DH2];
__device__ float    g_h2[NN * DH2];
__device__ unsigned g_h2t[NN * DH2];
__device__ float    g_Z[NN * DH2];
__device__ float4   g_rowvals[NN];
__device__ float4   g_colvals[NN];
__device__ float4   g_rowvals2[NN];
__device__ float4   g_colvals2[NN];
__device__ unsigned g_adjbits[NN * (NN / 32)];
__device__ float    g_pacc[8 * NN * DH1];    // layer0: 8 splits x N x 256 (exact)
__device__ float    g_pden[16 * NN];

// ---------------- pack adjacency into bitmask ----------------------------
__global__ void pack_adj_kernel(const int* __restrict__ adj, unsigned* __restrict__ bits) {
    int idx = blockIdx.x * 256 + threadIdx.x;
    unsigned b = __ballot_sync(0xffffffffu, adj[idx] > 0);
    if ((threadIdx.x & 31) == 0) bits[idx >> 5] = b;
}

// ---------------- tf32 mma GEMM with dual (fp32 + tf32) output -----------
template<int K>
__global__ __launch_bounds__(256) void gemmtf_kernel(
    const float* __restrict__ A, const float* __restrict__ B,
    float* __restrict__ C, unsigned* __restrict__ Ct, int N)
{
    __shared__ __align__(16) unsigned As[128 * 36];
    __shared__ __align__(16) unsigned Bs[32 * 68];
    const int tid = threadIdx.x, wid = tid >> 5, lane = tid & 31;
    const int grp = lane >> 2, tid4 = lane & 3;
    const int warpRow = wid & 3, warpCol = wid >> 2;
    const int m0 = blockIdx.x * 128, n0 = blockIdx.y * 64;

    float acc[2][4][4] = {};
    for (int k0 = 0; k0 < K; k0 += 32) {
        __syncthreads();
#pragma unroll
        for (int it = 0; it < 4; ++it) {
            int q = tid + it * 256;
            int r = q >> 3, c4 = (q & 7) * 4;
            float4 v = *(const float4*)&A[(size_t)(m0 + r) * K + k0 + c4];
            uint4 t;
            t.x = f2tf(v.x); t.y = f2tf(v.y); t.z = f2tf(v.z); t.w = f2tf(v.w);
            *(uint4*)&As[r * 36 + c4] = t;
        }
#pragma unroll
        for (int it = 0; it < 2; ++it) {
            int q = tid + it * 256;
            int r = q >> 4, c4 = (q & 15) * 4;
            float4 v = *(const float4*)&B[(size_t)(k0 + r) * N + n0 + c4];
            uint4 t;
            t.x = f2tf(v.x); t.y = f2tf(v.y); t.z = f2tf(v.z); t.w = f2tf(v.w);
            *(uint4*)&Bs[r * 68 + c4] = t;
        }
        __syncthreads();
#pragma unroll
        for (int kk = 0; kk < 4; ++kk) {
            int kb = kk * 8;
            unsigned af[2][4];
#pragma unroll
            for (int m = 0; m < 2; ++m) {
                int rb = (warpRow * 2 + m) * 16;
                af[m][0] = As[(rb + grp) * 36 + kb + tid4];
                af[m][1] = As[(rb + grp + 8) * 36 + kb + tid4];
                af[m][2] = As[(rb + grp) * 36 + kb + tid4 + 4];
                af[m][3] = As[(rb + grp + 8) * 36 + kb + tid4 + 4];
            }
#pragma unroll
            for (int n = 0; n < 4; ++n) {
                int nn = warpCol * 32 + n * 8;
                unsigned b0 = Bs[(kb + tid4) * 68 + nn + grp];
                unsigned b1 = Bs[(kb + tid4 + 4) * 68 + nn + grp];
                mma_tf32(acc[0][n], af[0], b0, b1);
                mma_tf32(acc[1][n], af[1], b0, b1);
            }
        }
    }
#pragma unroll
    for (int m = 0; m < 2; ++m) {
        int r0 = m0 + (warpRow * 2 + m) * 16 + grp;
#pragma unroll
        for (int n = 0; n < 4; ++n) {
            int col = n0 + warpCol * 32 + n * 8 + 2 * tid4;
            float a0 = acc[m][n][0], a1 = acc[m][n][1];
            float a2 = acc[m][n][2], a3 = acc[m][n][3];
            *(float2*)&C[(size_t)r0 * N + col] = make_float2(a0, a1);
            *(float2*)&C[(size_t)(r0 + 8) * N + col] = make_float2(a2, a3);
            *(uint2*)&Ct[(size_t)r0 * N + col] = make_uint2(f2tf(a0), f2tf(a1));
            *(uint2*)&Ct[(size_t)(r0 + 8) * N + col] = make_uint2(f2tf(a2), f2tf(a3));
        }
    }
}

// ---- fused dual-weight N=64 GEMM: blockIdx.y selects (W1,h1)/(W2,h2) ----
__global__ __launch_bounds__(256) void gemmtf2_kernel(
    const float* __restrict__ A,
    const float* __restrict__ B1, const float* __restrict__ B2,
    float* __restrict__ C1, unsigned* __restrict__ Ct1,
    float* __restrict__ C2, unsigned* __restrict__ Ct2)
{
    constexpr int K = DH1, N = DH2;
    const float* B = blockIdx.y ? B2 : B1;
    float* C = blockIdx.y ? C2 : C1;
    unsigned* Ct = blockIdx.y ? Ct2 : Ct1;

    __shared__ __align__(16) unsigned As[128 * 36];
    __shared__ __align__(16) unsigned Bs[32 * 68];
    const int tid = threadIdx.x, wid = tid >> 5, lane = tid & 31;
    const int grp = lane >> 2, tid4 = lane & 3;
    const int warpRow = wid & 3, warpCol = wid >> 2;
    const int m0 = blockIdx.x * 128;

    float acc[2][4][4] = {};
    for (int k0 = 0; k0 < K; k0 += 32) {
        __syncthreads();
#pragma unroll
        for (int it = 0; it < 4; ++it) {
            int q = tid + it * 256;
            int r = q >> 3, c4 = (q & 7) * 4;
            float4 v = *(const float4*)&A[(size_t)(m0 + r) * K + k0 + c4];
            uint4 t;
            t.x = f2tf(v.x); t.y = f2tf(v.y); t.z = f2tf(v.z); t.w = f2tf(v.w);
            *(uint4*)&As[r * 36 + c4] = t;
        }
#pragma unroll
        for (int it = 0; it < 2; ++it) {
            int q = tid + it * 256;
            int r = q >> 4, c4 = (q & 15) * 4;
            float4 v = *(const float4*)&B[(size_t)(k0 + r) * N + c4];
            uint4 t;
            t.x = f2tf(v.x); t.y = f2tf(v.y); t.z = f2tf(v.z); t.w = f2tf(v.w);
            *(uint4*)&Bs[r * 68 + c4] = t;
        }
        __syncthreads();
#pragma unroll
        for (int kk = 0; kk < 4; ++kk) {
            int kb = kk * 8;
            unsigned af[2][4];
#pragma unroll
            for (int m = 0; m < 2; ++m) {
                int rb = (warpRow * 2 + m) * 16;
                af[m][0] = As[(rb + grp) * 36 + kb + tid4];
                af[m][1] = As[(rb + grp + 8) * 36 + kb + tid4];
                af[m][2] = As[(rb + grp) * 36 + kb + tid4 + 4];
                af[m][3] = As[(rb + grp + 8) * 36 + kb + tid4 + 4];
            }
#pragma unroll
            for (int n = 0; n < 4; ++n) {
                int nn = warpCol * 32 + n * 8;
                unsigned b0 = Bs[(kb + tid4) * 68 + nn + grp];
                unsigned b1 = Bs[(kb + tid4 + 4) * 68 + nn + grp];
                mma_tf32(acc[0][n], af[0], b0, b1);
                mma_tf32(acc[1][n], af[1], b0, b1);
            }
        }
    }
#pragma unroll
    for (int m = 0; m < 2; ++m) {
        int r0 = m0 + (warpRow * 2 + m) * 16 + grp;
#pragma unroll
        for (int n = 0; n < 4; ++n) {
            int col = warpCol * 32 + n * 8 + 2 * tid4;
            float a0 = acc[m][n][0], a1 = acc[m][n][1];
            float a2 = acc[m][n][2], a3 = acc[m][n][3];
            *(float2*)&C[(size_t)r0 * N + col] = make_float2(a0, a1);
            *(float2*)&C[(size_t)(r0 + 8) * N + col] = make_float2(a2, a3);
            *(uint2*)&Ct[(size_t)r0 * N + col] = make_uint2(f2tf(a0), f2tf(a1));
            *(uint2*)&Ct[(size_t)(r0 + 8) * N + col] = make_uint2(f2tf(a2), f2tf(a3));
        }
    }
}

// ---------------- per-row attention scalars ------------------------------
__global__ void vals_kernel(const float* __restrict__ h, const float* __restrict__ a,
                            int D, float4* __restrict__ rowvals, float4* __restrict__ colvals)
{
    int warp = (blockIdx.x * blockDim.x + threadIdx.x) >> 5;
    int lane = threadIdx.x & 31;
    if (warp >= NN) return;
    float s1 = 0.f, s2 = 0.f;
    for (int d = lane; d < D; d += 32) {
        float hv = h[(size_t)warp * D + d];
        s1 += hv * a[d];
        s2 += hv * a[D + d];
    }
#pragma unroll
    for (int o = 16; o; o >>= 1) {
        s1 += __shfl_xor_sync(0xffffffffu, s1, o);
        s2 += __shfl_xor_sync(0xffffffffu, s2, o);
    }
    if (lane == 0) {
        rowvals[warp] = make_float4(-s1, expf(s1), expf(ALPHA * s1), 0.f);
        colvals[warp] = make_float4(s2, expf(s2), expf(ALPHA * s2), 0.f);
    }
}

// fused D=64 vals for both layers: blockIdx.y selects layer
__global__ void vals2_kernel(const float* __restrict__ h1, const float* __restrict__ a1,
                             const float* __restrict__ h2, const float* __restrict__ a2,
                             float4* __restrict__ rv1, float4* __restrict__ cv1,
                             float4* __restrict__ rv2, float4* __restrict__ cv2)
{
    const float* h = blockIdx.y ? h2 : h1;
    const float* a = blockIdx.y ? a2 : a1;
    float4* rowvals = blockIdx.y ? rv2 : rv1;
    float4* colvals = blockIdx.y ? cv2 : cv1;
    int warp = (blockIdx.x * blockDim.x + threadIdx.x) >> 5;
    int lane = threadIdx.x & 31;
    if (warp >= NN) return;
    float s1 = 0.f, s2 = 0.f;
    for (int d = lane; d < DH2; d += 32) {
        float hv = h[(size_t)warp * DH2 + d];
        s1 += hv * a[d];
        s2 += hv * a[DH2 + d];
    }
#pragma unroll
    for (int o = 16; o; o >>= 1) {
        s1 += __shfl_xor_sync(0xffffffffu, s1, o);
        s2 += __shfl_xor_sync(0xffffffffu, s2, o);
    }
    if (lane == 0) {
        rowvals[warp] = make_float4(-s1, expf(s1), expf(ALPHA * s1), 0.f);
        colvals[warp] = make_float4(s2, expf(s2), expf(ALPHA * s2), 0.f);
    }
}

// ---- attention vR64: weights-in-registers, BJ=64, 1 barrier per tile ----
// ROWG=8, COLG=1 (each warp: 16 rows x DC cols). Masks: 2 words/row-set/tile.
template<int D, int DC, int MAXB>
__global__ __launch_bounds__(256, MAXB) void attnR64_kernel(
    const unsigned* __restrict__ ht,
    const float4* __restrict__ rowvals,
    const float4* __restrict__ colvals,
    const unsigned* __restrict__ adjbits,
    float* __restrict__ pacc,
    float* __restrict__ pden)
{
    constexpr int BI = 128, BJ = 64;
    constexpr int DCp = DC + 8;
    constexpr int NT = DC / 8;
    constexpr int HS1 = BJ * DCp;
    constexpr int CP_IT = BJ * DC / (4 * 256);

    extern __shared__ __align__(16) unsigned smem_u[];
    unsigned* hs = smem_u;                         // [3][HS1]
    float4*   cvs = (float4*)(smem_u + 3 * HS1);   // [3][64]

    const int tid = threadIdx.x;
    const int wid = tid >> 5, lane = tid & 31;
    const int grp = lane >> 2, tid4 = lane & 3;
    const int rowbase = blockIdx.x * BI;
    const int colbase = blockIdx.y * DC;
    const int split = blockIdx.z;
    const int jcnt = NN / gridDim.z;
    const int jbeg = split * jcnt;
    const int T = jcnt / BJ;

    const int ra = rowbase + wid * 16 + grp;
    const float4 rva = rowvals[ra];
    const float4 rvb = rowvals[ra + 8];

    float acc[NT][4];
#pragma unroll
    for (int n = 0; n < NT; ++n)
#pragma unroll
        for (int q = 0; q < 4; ++q) acc[n][q] = 0.f;
    float denA = 0.f, denB = 0.f;

    auto cp_tile = [&](int t, int buf) {
        const int j0 = jbeg + t * BJ;
        unsigned* hb = hs + buf * HS1;
#pragma unroll
        for (int it = 0; it < CP_IT; ++it) {
            int q = tid + it * 256;
            int row = q / (DC / 4);
            int c = (q % (DC / 4)) * 4;
            cp_async16(&hb[row * DCp + c], &ht[(size_t)(j0 + row) * D + colbase + c]);
        }
        if (tid < BJ) cp_async16(&cvs[buf * BJ + tid], &colvals[j0 + tid]);
    };

    auto phase = [&](int buf, const unsigned* ma, const unsigned* mb) {
        const float4* cv = cvs + buf * BJ;
        const unsigned* hb = hs + buf * HS1;
#pragma unroll
        for (int kb = 0; kb < BJ; kb += 8) {
            const int w = kb >> 5;
            const int j1 = (kb & 31) + tid4, j2 = j1 + 4;
            float4 c1 = cv[kb + tid4];
            float4 c2 = cv[kb + tid4 + 4];
            float w0 = (c1.x > rva.x) ? (rva.y * c1.y) : (rva.z * c1.z);
            float w1 = (c1.x > rvb.x) ? (rvb.y * c1.y) : (rvb.z * c1.z);
            float w2 = (c2.x > rva.x) ? (rva.y * c2.y) : (rva.z * c2.z);
            float w3 = (c2.x > rvb.x) ? (rvb.y * c2.y) : (rvb.z * c2.z);
            w0 = ((ma[w] >> j1) & 1u) ? w0 : 0.f;
            w1 = ((mb[w] >> j1) & 1u) ? w1 : 0.f;
            w2 = ((ma[w] >> j2) & 1u) ? w2 : 0.f;
            w3 = ((mb[w] >> j2) & 1u) ? w3 : 0.f;
            denA += w0 + w2;
            denB += w1 + w3;
            unsigned afr[4];
            afr[0] = f2tf(w0); afr[1] = f2tf(w1);
            afr[2] = f2tf(w2); afr[3] = f2tf(w3);
#pragma unroll
            for (int n = 0; n < NT; ++n) {
                int n0 = n * 8;
                unsigned b0 = hb[(kb + tid4) * DCp + n0 + grp];
                unsigned b1 = hb[(kb + tid4 + 4) * DCp + n0 + grp];
                mma_tf32(acc[n], afr, b0, b1);
            }
        }
    };

    unsigned ma[2], mb[2], ma_n[2], mb_n[2];
    cp_tile(0, 0);
    CP_COMMIT();
    {
        const int w0 = jbeg >> 5;
        ma[0] = adjbits[(size_t)ra * (NN / 32) + w0];
        ma[1] = adjbits[(size_t)ra * (NN / 32) + w0 + 1];
        mb[0] = adjbits[(size_t)(ra + 8) * (NN / 32) + w0];
        mb[1] = adjbits[(size_t)(ra + 8) * (NN / 32) + w0 + 1];
    }

    for (int t = 0; t < T; ++t) {
        const bool more = (t + 1 < T);
        if (more) {
            cp_tile(t + 1, (t + 1) % 3);
            CP_COMMIT();
            const int wN = (jbeg + (t + 1) * BJ) >> 5;
            ma_n[0] = adjbits[(size_t)ra * (NN / 32) + wN];
            ma_n[1] = adjbits[(size_t)ra * (NN / 32) + wN + 1];
            mb_n[0] = adjbits[(size_t)(ra + 8) * (NN / 32) + wN];
            mb_n[1] = adjbits[(size_t)(ra + 8) * (NN / 32) + wN + 1];
            CP_WAIT1();              // tile t's group complete (t+1 in flight)
        } else {
            CP_WAIT0();
        }
        __syncthreads();             // tile t visible; ring buf (t+1)%3 fenced (last read t-2)
        phase(t % 3, ma, mb);
        ma[0] = ma_n[0]; ma[1] = ma_n[1];
        mb[0] = mb_n[0]; mb[1] = mb_n[1];
    }

    // epilogue
#pragma unroll
    for (int n = 0; n < NT; ++n) {
        int col = colbase + n * 8 + 2 * tid4;
        float* p0 = pacc + ((size_t)split * NN + ra) * D + col;
        float* p1 = pacc + ((size_t)split * NN + ra + 8) * D + col;
        *(float2*)p0 = make_float2(acc[n][0], acc[n][1]);
        *(float2*)p1 = make_float2(acc[n][2], acc[n][3]);
    }
    if (blockIdx.y == 0) {
        float da = denA, db = denB;
        da += __shfl_xor_sync(0xffffffffu, da, 1);
        da += __shfl_xor_sync(0xffffffffu, da, 2);
        db += __shfl_xor_sync(0xffffffffu, db, 1);
        db += __shfl_xor_sync(0xffffffffu, db, 2);
        if (tid4 == 0) {
            pden[split * NN + ra] = da;
            pden[split * NN + ra + 8] = db;
        }
    }
}

// ---------------- fused D=64 attention, BJ=64, layer via blockIdx.y ------
__global__ __launch_bounds__(256, 3) void attn64R_kernel(
    const unsigned* __restrict__ ht0, const unsigned* __restrict__ ht1,
    const float4* __restrict__ rv0, const float4* __restrict__ cv0,
    const float4* __restrict__ rv1, const float4* __restrict__ cv1,
    const unsigned* __restrict__ adjbits,
    float* __restrict__ pacc,
    float* __restrict__ pden)
{
    constexpr int BI = 128, BJ = 64, DC = 64, DCp = 72;
    constexpr int NT = 8;
    constexpr int HS1 = BJ * DCp;
    constexpr int CP_IT = 4;

    extern __shared__ __align__(16) unsigned smem_u[];
    unsigned* hs = smem_u;
    float4*   cvs = (float4*)(smem_u + 3 * HS1);

    const int tid = threadIdx.x;
    const int wid = tid >> 5, lane = tid & 31;
    const int grp = lane >> 2, tid4 = lane & 3;
    const int rowbase = blockIdx.x * BI;
    const int layer = blockIdx.y;
    const int split = blockIdx.z;
    const int jcnt = NN / gridDim.z;
    const int jbeg = split * jcnt;
    const int T = jcnt / BJ;

    const unsigned* ht = layer ? ht1 : ht0;
    const float4* rowvals = layer ? rv1 : rv0;
    const float4* colvals = layer ? cv1 : cv0;
    float* pacc_l = pacc + (size_t)layer * 8 * NN * DC;
    float* pden_l = pden + (size_t)layer * 8 * NN;

    const int ra = rowbase + wid * 16 + grp;
    const float4 rva = rowvals[ra];
    const float4 rvb = rowvals[ra + 8];

    float acc[NT][4];
#pragma unroll
    for (int n = 0; n < NT; ++n)
#pragma unroll
        for (int q = 0; q < 4; ++q) acc[n][q] = 0.f;
    float denA = 0.f, denB = 0.f;

    auto cp_tile = [&](int t, int buf) {
        const int j0 = jbeg + t * BJ;
        unsigned* hb = hs + buf * HS1;
#pragma unroll
        for (int it = 0; it < CP_IT; ++it) {
            int q = tid + it * 256;
            int row = q >> 4;
            int c = (q & 15) * 4;
            cp_async16(&hb[row * DCp + c], &ht[(size_t)(j0 + row) * DC + c]);
        }
        if (tid < BJ) cp_async16(&cvs[buf * BJ + tid], &colvals[j0 + tid]);
    };

    auto phase = [&](int buf, const unsigned* ma, const unsigned* mb) {
        const float4* cv = cvs + buf * BJ;
        const unsigned* hb = hs + buf * HS1;
#pragma unroll
        for (int kb = 0; kb < BJ; kb += 8) {
            const int w = kb >> 5;
            const int j1 = (kb & 31) + tid4, j2 = j1 + 4;
            float4 c1 = cv[kb + tid4];
            float4 c2 = cv[kb + tid4 + 4];
            float w0 = (c1.x > rva.x) ? (rva.y * c1.y) : (rva.z * c1.z);
            float w1 = (c1.x > rvb.x) ? (rvb.y * c1.y) : (rvb.z * c1.z);
            float w2 = (c2.x > rva.x) ? (rva.y * c2.y) : (rva.z * c2.z);
            float w3 = (c2.x > rvb.x) ? (rvb.y * c2.y) : (rvb.z * c2.z);
            w0 = ((ma[w] >> j1) & 1u) ? w0 : 0.f;
            w1 = ((mb[w] >> j1) & 1u) ? w1 : 0.f;
            w2 = ((ma[w] >> j2) & 1u) ? w2 : 0.f;
            w3 = ((mb[w] >> j2) & 1u) ? w3 : 0.f;
            denA += w0 + w2;
            denB += w1 + w3;
            unsigned afr[4];
            afr[0] = f2tf(w0); afr[1] = f2tf(w1);
            afr[2] = f2tf(w2); afr[3] = f2tf(w3);
#pragma unroll
            for (int n = 0; n < NT; ++n) {
                int n0 = n * 8;
                unsigned b0 = hb[(kb + tid4) * DCp + n0 + grp];
                unsigned b1 = hb[(kb + tid4 + 4) * DCp + n0 + grp];
                mma_tf32(acc[n], afr, b0, b1);
            }
        }
    };

    unsigned ma[2], mb[2], ma_n[2], mb_n[2];
    cp_tile(0, 0);
    CP_COMMIT();
    {
        const int w0 = jbeg >> 5;
        ma[0] = adjbits[(size_t)ra * (NN / 32) + w0];
        ma[1] = adjbits[(size_t)ra * (NN / 32) + w0 + 1];
        mb[0] = adjbits[(size_t)(ra + 8) * (NN / 32) + w0];
        mb[1] = adjbits[(size_t)(ra + 8) * (NN / 32) + w0 + 1];
    }

    for (int t = 0; t < T; ++t) {
        const bool more = (t + 1 < T);
        if (more) {
            cp_tile(t + 1, (t + 1) % 3);
            CP_COMMIT();
            const int wN = (jbeg + (t + 1) * BJ) >> 5;
            ma_n[0] = adjbits[(size_t)ra * (NN / 32) + wN];
            ma_n[1] = adjbits[(size_t)ra * (NN / 32) + wN + 1];
            mb_n[0] = adjbits[(size_t)(ra + 8) * (NN / 32) + wN];
            mb_n[1] = adjbits[(size_t)(ra + 8) * (NN / 32) + wN + 1];
            CP_WAIT1();
        } else {
            CP_WAIT0();
        }
        __syncthreads();
        phase(t % 3, ma, mb);
        ma[0] = ma_n[0]; ma[1] = ma_n[1];
        mb[0] = mb_n[0]; mb[1] = mb_n[1];
    }

#pragma unroll
    for (int n = 0; n < NT; ++n) {
        int col = n * 8 + 2 * tid4;
        float* p0 = pacc_l + ((size_t)split * NN + ra) * DC + col;
        float* p1 = pacc_l + ((size_t)split * NN + ra + 8) * DC + col;
        *(float2*)p0 = make_float2(acc[n][0], acc[n][1]);
        *(float2*)p1 = make_float2(acc[n][2], acc[n][3]);
    }
    {
        float da = denA, db = denB;
        da += __shfl_xor_sync(0xffffffffu, da, 1);
        da += __shfl_xor_sync(0xffffffffu, da, 2);
        db += __shfl_xor_sync(0xffffffffu, db, 1);
        db += __shfl_xor_sync(0xffffffffu, db, 2);
        if (tid4 == 0) {
            pden_l[split * NN + ra] = da;
            pden_l[split * NN + ra + 8] = db;
        }
    }
}

// ---------------- combine split partials + normalize (layer 0) -----------
__global__ void combine_kernel(const float* __restrict__ pacc, const float* __restrict__ pden,
                               float* __restrict__ out, int D, int nsplit)
{
    int idx = blockIdx.x * blockDim.x + threadIdx.x;
    int total = NN * D / 4;
    if (idx >= total) return;
    int row = idx / (D / 4);
    float4 s = make_float4(0.f, 0.f, 0.f, 0.f);
    float dd = 0.f;
    for (int sp = 0; sp < nsplit; ++sp) {
        float4 v = ((const float4*)pacc)[(size_t)sp * total + idx];
        s.x += v.x; s.y += v.y; s.z += v.z; s.w += v.w;
        dd += pden[sp * NN + row];
    }
    float inv = 1.f / dd;
    s.x *= inv; s.y *= inv; s.z *= inv; s.w *= inv;
    ((float4*)out)[idx] = s;
}

// ---------------- combine both D=64 layers + Z in one pass ---------------
__global__ void combine_z_kernel(const float* __restrict__ pacc, const float* __restrict__ pden,
                                 const float* __restrict__ noise, float* __restrict__ Z)
{
    int idx = blockIdx.x * blockDim.x + threadIdx.x;
    const int total = NN * DH2 / 4;
    if (idx >= total) return;
    int row = idx / (DH2 / 4);
    const float4* pm = (const float4*)pacc;
    const float4* pl = (const float4*)(pacc + (size_t)8 * NN * DH2);
    float4 m = make_float4(0.f, 0.f, 0.f, 0.f);
    float4 l = make_float4(0.f, 0.f, 0.f, 0.f);
    float dm = 0.f, dl = 0.f;
    for (int sp = 0; sp < 8; ++sp) {
        float4 v = pm[(size_t)sp * total + idx];
        m.x += v.x; m.y += v.y; m.z += v.z; m.w += v.w;
        float4 u = pl[(size_t)sp * total + idx];
        l.x += u.x; l.y += u.y; l.z += u.z; l.w += u.w;
        dm += pden[sp * NN + row];
        dl += pden[8 * NN + sp * NN + row];
    }
    float im = 1.f / dm, il = 1.f / dl;
    float4 nz = ((const float4*)noise)[idx];
    float4 z;
    z.x = nz.x * fast_exp(l.x * il) + m.x * im;
    z.y = nz.y * fast_exp(l.y * il) + m.y * im;
    z.z = nz.z * fast_exp(l.z * il) + m.z * im;
    z.w = nz.w * fast_exp(l.w * il) + m.w * im;
    ((float4*)Z)[idx] = z;
}

// ---------------- A = sigmoid(Z @ Z^T): tf32 mma, coalesced mirror -------
__global__ __launch_bounds__(256, 2) void zzt2_kernel(const float* __restrict__ Z,
                                                      float* __restrict__ out)
{
    const int bi = blockIdx.y, bj = blockIdx.x;
    if (bj < bi) return;
    extern __shared__ __align__(16) unsigned zs[];
    unsigned* Zi = zs;
    unsigned* Zj = zs + 128 * 68;
    const int tid = threadIdx.x, wid = tid >> 5, lane = tid & 31;
    const int grp = lane >> 2, tid4 = lane & 3;
    const int warpRow = wid & 3, warpCol = wid >> 2;
    const int i0 = bi * 128, j0 = bj * 128;

#pragma unroll
    for (int it = 0; it < 16; ++it) {
        int q = tid + it * 256;
        int tile = q >> 11;
        int qq = q & 2047;
        int r = qq >> 4, c4 = (qq & 15) * 4;
        int gr = (tile ? j0 : i0) + r;
        float4 v = *(const float4*)&Z[(size_t)gr * DH2 + c4];
        uint4 t;
        t.x = f2tf(v.x); t.y = f2tf(v.y); t.z = f2tf(v.z); t.w = f2tf(v.w);
        *(uint4*)&((tile ? Zj : Zi)[r * 68 + c4]) = t;
    }
    __syncthreads();

    float acc[2][8][4] = {};
#pragma unroll
    for (int kk = 0; kk < 8; ++kk) {
        int kb = kk * 8;
        unsigned af[2][4];
#pragma unroll
        for (int m = 0; m < 2; ++m) {
            int rb = (warpRow * 2 + m) * 16;
            af[m][0] = Zi[(rb + grp) * 68 + kb + tid4];
            af[m][1] = Zi[(rb + grp + 8) * 68 + kb + tid4];
            af[m][2] = Zi[(rb + grp) * 68 + kb + tid4 + 4];
            af[m][3] = Zi[(rb + grp + 8) * 68 + kb + tid4 + 4];
        }
#pragma unroll
        for (int n = 0; n < 8; ++n) {
            int nn = warpCol * 64 + n * 8;
            unsigned b0 = Zj[(nn + grp) * 68 + kb + tid4];
            unsigned b1 = Zj[(nn + grp) * 68 + kb + tid4 + 4];
#pragma unroll
            for (int m = 0; m < 2; ++m)
                mma_tf32(acc[m][n], af[m], b0, b1);
        }
    }

#pragma unroll
    for (int m = 0; m < 2; ++m) {
        int r0 = i0 + (warpRow * 2 + m) * 16 + grp;
#pragma unroll
        for (int n = 0; n < 8; ++n) {
            int col = j0 + warpCol * 64 + n * 8 + 2 * tid4;
#pragma unroll
            for (int q = 0; q < 4; ++q) acc[m][n][q] = fast_sigmoid(acc[m][n][q]);
            *(float2*)&out[(size_t)r0 * NN + col] = make_float2(acc[m][n][0], acc[m][n][1]);
            *(float2*)&out[(size_t)(r0 + 8) * NN + col] = make_float2(acc[m][n][2], acc[m][n][3]);
        }
    }

    if (bj > bi) {
        __syncthreads();
        float* sT = (float*)zs;
#pragma unroll
        for (int m = 0; m < 2; ++m) {
            int lr0 = (warpRow * 2 + m) * 16 + grp;
#pragma unroll
            for (int n = 0; n < 8; ++n) {
                int lc = warpCol * 64 + n * 8 + 2 * tid4;
                sT[(size_t)lc * 132 + lr0] = acc[m][n][0];
                sT[(size_t)(lc + 1) * 132 + lr0] = acc[m][n][1];
                sT[(size_t)lc * 132 + lr0 + 8] = acc[m][n][2];
                sT[(size_t)(lc + 1) * 132 + lr0 + 8] = acc[m][n][3];
            }
        }
        __syncthreads();
#pragma unroll
        for (int it = 0; it < 16; ++it) {
            int q = tid + it * 256;
            int rr = q >> 5, cc = (q & 31) * 4;
            float4 v = *(float4*)&sT[(size_t)rr * 132 + cc];
            *(float4*)&out[(size_t)(j0 + rr) * NN + i0 + cc] = v;
        }
    }
}

// ---------------- host orchestration -------------------------------------
extern "C" void kernel_launch(void* const* d_in, const int* in_sizes, int n_in,
                              void* d_out, int out_size)
{
    const float* X     = (const float*)d_in[0];
    const int*   adj   = (const int*)  d_in[1];
    const float* noise = (const float*)d_in[2];
    const float* W0    = (const float*)d_in[3];
    const float* a0    = (const float*)d_in[4];
    const float* W1    = (const float*)d_in[5];
    const float* a1    = (const float*)d_in[6];
    const float* W2    = (const float*)d_in[7];
    const float* a2    = (const float*)d_in[8];
    float* out = (float*)d_out;

    float *p_h0, *p_hidden, *p_h1, *p_h2, *p_Z, *p_pacc, *p_pden;
    unsigned *p_h0t, *p_h1t, *p_h2t;
    float4 *p_rv, *p_cv, *p_rv2, *p_cv2;
    unsigned* p_bits;
    cudaGetSymbolAddress((void**)&p_h0, g_h0);
    cudaGetSymbolAddress((void**)&p_h0t, g_h0t);
    cudaGetSymbolAddress((void**)&p_hidden, g_hidden);
    cudaGetSymbolAddress((void**)&p_h1, g_h1);
    cudaGetSymbolAddress((void**)&p_h1t, g_h1t);
    cudaGetSymbolAddress((void**)&p_h2, g_h2);
    cudaGetSymbolAddress((void**)&p_h2t, g_h2t);
    cudaGetSymbolAddress((void**)&p_Z, g_Z);
    cudaGetSymbolAddress((void**)&p_pacc, g_pacc);
    cudaGetSymbolAddress((void**)&p_pden, g_pden);
    cudaGetSymbolAddress((void**)&p_rv, g_rowvals);
    cudaGetSymbolAddress((void**)&p_cv, g_colvals);
    cudaGetSymbolAddress((void**)&p_rv2, g_rowvals2);
    cudaGetSymbolAddress((void**)&p_cv2, g_colvals2);
    cudaGetSymbolAddress((void**)&p_bits, g_adjbits);

    // smem: 3 * hs(64*(DC+8)) words + cvs(3*64*16B)
    const int smem256 = (3 * 64 * 136) * 4 + 3 * 64 * 16;   // 107520
    const int smem64  = (3 * 64 * 72) * 4 + 3 * 64 * 16;    // 58368
    const int smemZZ  = 2 * 128 * 68 * 4;                   // 69632
    cudaFuncSetAttribute((const void*)attnR64_kernel<DH1, 128, 2>,
                         cudaFuncAttributeMaxDynamicSharedMemorySize, smem256);
    cudaFuncSetAttribute((const void*)attn64R_kernel,
                         cudaFuncAttributeMaxDynamicSharedMemorySize, smem64);
    cudaFuncSetAttribute((const void*)zzt2_kernel,
                         cudaFuncAttributeMaxDynamicSharedMemorySize, smemZZ);

    pack_adj_kernel<<<NN * NN / 256, 256>>>(adj, p_bits);

    // ---- layer 0 ----
    gemmtf_kernel<DIN><<<dim3(NN / 128, DH1 / 64), 256>>>(X, W0, p_h0, p_h0t, DH1);
    vals_kernel<<<NN / 8, 256>>>(p_h0, a0, DH1, p_rv, p_cv);
    attnR64_kernel<DH1, 128, 2><<<dim3(NN / 128, 2, 8), 256, smem256>>>(p_h0t, p_rv, p_cv, p_bits, p_pacc, p_pden);
    combine_kernel<<<NN * DH1 / 4 / 256, 256>>>(p_pacc, p_pden, p_hidden, DH1, 8);

    // ---- layers 1+2 fused ----
    gemmtf2_kernel<<<dim3(NN / 128, 2), 256>>>(p_hidden, W1, W2, p_h1, p_h1t, p_h2, p_h2t);
    vals2_kernel<<<dim3(NN / 8, 2), 256>>>(p_h1, a1, p_h2, a2, p_rv, p_cv, p_rv2, p_cv2);
    attn64R_kernel<<<dim3(NN / 128, 2, 8), 256, smem64>>>(p_h1t, p_h2t, p_rv, p_cv, p_rv2, p_cv2, p_bits, p_pacc, p_pden);
    combine_z_kernel<<<NN * DH2 / 4 / 256, 256>>>(p_pacc, p_pden, noise, p_Z);

    // ---- decoder ----
    zzt2_kernel<<<dim3(NN / 128, NN / 128), 256, smemZZ>>>(p_Z, out);
}